// round 1
// baseline (speedup 1.0000x reference)
#include <cuda_runtime.h>
#include <cuda_bf16.h>

// ---------------- problem constants ----------------
#define H_IMG   2048
#define W_IMG   2048
#define C_IMG   3
#define RAD     5
#define NITER   10
#define PH      (H_IMG + 2*RAD)   // 2058
#define PW      (W_IMG + 2*RAD)   // 2058
#define PITCH   2080              // row pitch in floats (8320 B, 128B-aligned)
#define PLANE   (PH * PITCH)      // floats per channel plane
#define BUFSZ   (C_IMG * PLANE)   // floats per ping-pong buffer

// Ping-pong state buffers (allocation-free scratch).
__device__ float g_U[2][BUFSZ];

// ---------------- pad (edge replicate) HWC -> planar padded ----------------
__global__ void swf_pad(const float* __restrict__ img) {
    int total = C_IMG * PH * PW;
    for (int i = blockIdx.x * blockDim.x + threadIdx.x; i < total;
         i += gridDim.x * blockDim.x) {
        int x = i % PW;
        int t = i / PW;
        int y = t % PH;
        int c = t / PH;
        int sy = y - RAD; sy = sy < 0 ? 0 : (sy > H_IMG - 1 ? H_IMG - 1 : sy);
        int sx = x - RAD; sx = sx < 0 ? 0 : (sx > W_IMG - 1 ? W_IMG - 1 : sx);
        g_U[0][c * PLANE + y * PITCH + x] = img[(sy * W_IMG + sx) * C_IMG + c];
    }
}

// ---------------- one side-window iteration (fused, smem tiled) ----------------
#define TH 32
#define TW 128
#define SW (TW + 2*RAD)          // 138: tile width incl. halo

__global__ __launch_bounds__(256)
void swf_iter(int s) {
    const float* __restrict__ S = g_U[s];
    float* __restrict__ D = g_U[s ^ 1];

    __shared__ float tile[(TH + 2*RAD) * SW];   // 42 x 138 input with halo
    __shared__ float sV[(TH + RAD) * SW];       // 37 x 138 vertical 6-sums

    const int c  = blockIdx.z;
    const int x0 = blockIdx.x * TW;
    const int y0 = blockIdx.y * TH;
    const int tx = threadIdx.x;                 // 0..31
    const int ty = threadIdx.y;                 // 0..7
    const float* __restrict__ Sp = S + c * PLANE;
    float* __restrict__ Dp = D + c * PLANE;

    // Load input tile with halo; zero outside the padded field (conv zero-pad).
    for (int ly = ty; ly < TH + 2*RAD; ly += 8) {
        int gy = y0 - RAD + ly;
        bool yok = (gy >= 0) && (gy < PH);
        for (int lx = tx; lx < SW; lx += 32) {
            int gx = x0 - RAD + lx;
            float v = 0.0f;
            if (yok && gx >= 0 && gx < PW) v = Sp[gy * PITCH + gx];
            tile[ly * SW + lx] = v;
        }
    }
    __syncthreads();

    // Vertical extended 6-sums: sV[ly] = sum of tile rows ly..ly+5.
    // Then sumUp(out row ly) = sV[ly], sumDown(out row ly) = sV[ly+5].
    for (int ly = ty; ly < TH + RAD; ly += 8) {
        for (int lx = tx; lx < SW; lx += 32) {
            float a = 0.0f;
            #pragma unroll
            for (int k = 0; k < 6; k++) a += tile[(ly + k) * SW + lx];
            sV[ly * SW + lx] = a;
        }
    }
    __syncthreads();

    const float i36 = 1.0f / 36.0f;
    const float i66 = 1.0f / 66.0f;

    for (int ly = ty; ly < TH; ly += 8) {
        int gy = y0 + ly;
        if (gy >= PH) continue;
        for (int lx = tx; lx < TW; lx += 32) {
            int gx = x0 + lx;
            if (gx >= PW) continue;

            const float* uRow = &sV[ly * SW + lx];          // vertical up-sum row
            const float* dRow = &sV[(ly + RAD) * SW + lx];  // vertical down-sum row
            const float* hRow = &tile[(ly + RAD) * SW + lx];// center pixel row

            float c0 = hRow[RAD];

            float uL = 0.f, uR = 0.f, dL = 0.f, dR = 0.f, hL = 0.f, hR = 0.f;
            #pragma unroll
            for (int k = 0; k < 6; k++) {
                uL += uRow[k]; dL += dRow[k]; hL += hRow[k];
            }
            #pragma unroll
            for (int k = 5; k < 11; k++) {
                uR += uRow[k]; dR += dRow[k]; hR += hRow[k];
            }
            float uF = uL + uR - uRow[RAD];   // up 6 rows x 11 cols
            float dF = dL + dR - dRow[RAD];   // down 6 rows x 11 cols
            float fL = uL + dL - hL;          // 11 rows x left 6 cols
            float fR = uR + dR - hR;          // 11 rows x right 6 cols

            // Candidate averages in reference kernel-stack order:
            // [LL, LR, RL, RR, L*k, R*k, k*L, k*R]
            float cand0 = uL * i36;
            float cand1 = uR * i36;
            float cand2 = dL * i36;
            float cand3 = dR * i36;
            float cand4 = uF * i66;
            float cand5 = dF * i66;
            float cand6 = fL * i66;
            float cand7 = fR * i66;

            float bd = cand0 - c0;
            float ba = fabsf(bd);
            float di, ai;
            di = cand1 - c0; ai = fabsf(di); if (ai < ba) { ba = ai; bd = di; }
            di = cand2 - c0; ai = fabsf(di); if (ai < ba) { ba = ai; bd = di; }
            di = cand3 - c0; ai = fabsf(di); if (ai < ba) { ba = ai; bd = di; }
            di = cand4 - c0; ai = fabsf(di); if (ai < ba) { ba = ai; bd = di; }
            di = cand5 - c0; ai = fabsf(di); if (ai < ba) { ba = ai; bd = di; }
            di = cand6 - c0; ai = fabsf(di); if (ai < ba) { ba = ai; bd = di; }
            di = cand7 - c0; ai = fabsf(di); if (ai < ba) { ba = ai; bd = di; }

            Dp[gy * PITCH + gx] = c0 + bd;
        }
    }
}

// ---------------- crop planar padded -> HWC output ----------------
__global__ void swf_crop(float* __restrict__ out) {
    int total = H_IMG * W_IMG * C_IMG;
    for (int i = blockIdx.x * blockDim.x + threadIdx.x; i < total;
         i += gridDim.x * blockDim.x) {
        int c = i % C_IMG;
        int t = i / C_IMG;
        int x = t % W_IMG;
        int y = t / W_IMG;
        out[i] = g_U[0][c * PLANE + (y + RAD) * PITCH + (x + RAD)];
    }
}

extern "C" void kernel_launch(void* const* d_in, const int* in_sizes, int n_in,
                              void* d_out, int out_size) {
    const float* img = (const float*)d_in[0];   // (2048,2048,3) f32; kernel input d_in[1] unused (hardcoded)
    float* out = (float*)d_out;

    {
        int total = C_IMG * PH * PW;
        int threads = 256;
        int blocks = (total + threads - 1) / threads;
        if (blocks > 65535) blocks = 65535;
        swf_pad<<<blocks, threads>>>(img);
    }

    dim3 block(32, 8);
    dim3 grid((PW + TW - 1) / TW, (PH + TH - 1) / TH, C_IMG);
    for (int i = 0; i < NITER; i++) {
        swf_iter<<<grid, block>>>(i & 1);
    }

    {
        int total = H_IMG * W_IMG * C_IMG;
        int threads = 256;
        int blocks = (total + threads - 1) / threads;
        if (blocks > 65535) blocks = 65535;
        swf_crop<<<blocks, threads>>>(out);
    }
}

// round 2
// speedup vs baseline: 1.0739x; 1.0739x over previous
#include <cuda_runtime.h>
#include <cuda_bf16.h>

// ---------------- problem constants ----------------
#define H_IMG   2048
#define W_IMG   2048
#define C_IMG   3
#define RAD     5
#define NITER   10
#define PH      (H_IMG + 2*RAD)   // 2058
#define PW      (W_IMG + 2*RAD)   // 2058
#define PITCH   2080              // row pitch in floats (8320 B, 128B-aligned)
#define PLANE   (PH * PITCH)      // floats per channel plane
#define BUFSZ   (C_IMG * PLANE)   // floats per ping-pong buffer

// Ping-pong state buffers (allocation-free scratch).
__device__ float g_U[2][BUFSZ];

// ---------------- pad (edge replicate) HWC -> planar padded ----------------
__global__ void swf_pad(const float* __restrict__ img) {
    int total = C_IMG * PH * PW;
    for (int i = blockIdx.x * blockDim.x + threadIdx.x; i < total;
         i += gridDim.x * blockDim.x) {
        int x = i % PW;
        int t = i / PW;
        int y = t % PH;
        int c = t / PH;
        int sy = y - RAD; sy = sy < 0 ? 0 : (sy > H_IMG - 1 ? H_IMG - 1 : sy);
        int sx = x - RAD; sx = sx < 0 ? 0 : (sx > W_IMG - 1 ? W_IMG - 1 : sx);
        g_U[0][c * PLANE + y * PITCH + x] = img[(sy * W_IMG + sx) * C_IMG + c];
    }
}

// ---------------- one side-window iteration ----------------
// Tile: TH x TW outputs. tile[] holds input with full halo (TH+10 x TW+10).
// h6[] holds horizontal extended 6-sums: h6[r][c] = sum tile[r][c..c+5].
// Final stage: per-thread vertical walk with register ring buffers.
#define TH 32
#define TW 128
#define TROWS (TH + 2*RAD)       // 42
#define TCOLS (TW + 2*RAD)       // 138
#define H6W   (TW + RAD)         // 133

__global__ __launch_bounds__(256)
void swf_iter(int s) {
    const float* __restrict__ S = g_U[s];
    float* __restrict__ D = g_U[s ^ 1];

    __shared__ float tile[TROWS * TCOLS];   // 42*138 = 5796 floats
    __shared__ float h6[TROWS * H6W];       // 42*133 = 5586 floats

    const int c  = blockIdx.z;
    const int x0 = blockIdx.x * TW;
    const int y0 = blockIdx.y * TH;
    const int t  = threadIdx.x;             // 0..255
    const int tx = t & 31;
    const int ty = t >> 5;
    const float* __restrict__ Sp = S + c * PLANE;
    float* __restrict__ Dp = D + c * PLANE;

    // ---- Stage 1: load input tile with halo (zero outside padded field) ----
    for (int ly = ty; ly < TROWS; ly += 8) {
        int gy = y0 - RAD + ly;
        bool yok = (gy >= 0) && (gy < PH);
        const float* rowp = Sp + gy * PITCH;
        for (int lx = tx; lx < TCOLS; lx += 32) {
            int gx = x0 - RAD + lx;
            float v = 0.0f;
            if (yok && gx >= 0 && gx < PW) v = rowp[gx];
            tile[ly * TCOLS + lx] = v;
        }
    }
    __syncthreads();

    // ---- Stage 2: horizontal extended 6-sums via per-thread sliding window ----
    // 42 rows x 6 segments of <=23 cols each = 252 active threads.
    if (t < 252) {
        int r   = t / 6;
        int seg = t - r * 6;
        int sx  = seg * 23;
        int ex  = sx + 23; if (ex > H6W) ex = H6W;
        const float* trow = &tile[r * TCOLS];
        float* hrow = &h6[r * H6W];
        float sum = 0.0f;
        #pragma unroll
        for (int k = 0; k < 6; k++) sum += trow[sx + k];
        hrow[sx] = sum;
        for (int cc = sx + 1; cc < ex; cc++) {
            sum += trow[cc + 5] - trow[cc - 1];
            hrow[cc] = sum;
        }
    }
    __syncthreads();

    // ---- Stage 3: vertical walk. 128 columns x 2 row-halves = 256 threads ----
    const int lx   = t & 127;        // output column within tile
    const int half = t >> 7;         // 0 or 1
    const int base = half * (TH / 2);  // first output row of this half (local)

    const int gx = x0 + lx;
    const bool xok = (gx < PW);

    const float i36 = 1.0f / 36.0f;
    const float i66 = 1.0f / 66.0f;

    // Ring buffers over tile/h6 rows base .. base+25 (12 live at a time).
    float rHL[12], rHR[12], rC[12];

    #pragma unroll
    for (int i = 0; i < 11; i++) {
        int row = base + i;
        rHL[i] = h6[row * H6W + lx];
        rHR[i] = h6[row * H6W + lx + 5];
        rC[i]  = tile[row * TCOLS + lx + 5];
    }

    float uL = 0.f, uR = 0.f, Vu = 0.f, dL = 0.f, dR = 0.f, Vd = 0.f;
    #pragma unroll
    for (int i = 0; i < 6; i++)  { uL += rHL[i]; uR += rHR[i]; Vu += rC[i]; }
    #pragma unroll
    for (int i = 5; i < 11; i++) { dL += rHL[i]; dR += rHR[i]; Vd += rC[i]; }

    #pragma unroll
    for (int ly = 0; ly < TH / 2; ly++) {
        if (ly > 0) {
            const int slot = (10 + ly) % 12;
            const int row  = base + 10 + ly;
            float nHL = h6[row * H6W + lx];
            float nHR = h6[row * H6W + lx + 5];
            float nC  = tile[row * TCOLS + lx + 5];
            const int du = (ly - 1) % 12;        // row leaving the "up" window
            const int au = (5 + ly) % 12;        // row entering the "up" window
            const int dd = (4 + ly) % 12;        // row leaving the "down" window
            uL += rHL[au] - rHL[du];
            uR += rHR[au] - rHR[du];
            Vu += rC[au]  - rC[du];
            dL += nHL - rHL[dd];
            dR += nHR - rHR[dd];
            Vd += nC  - rC[dd];
            rHL[slot] = nHL; rHR[slot] = nHR; rC[slot] = nC;
        }

        const int cs = (5 + ly) % 12;
        const float c0 = rC[cs];
        const float hL = rHL[cs];
        const float hR = rHR[cs];

        const float uF = uL + uR - Vu;    // up 6 rows x 11 cols
        const float dF = dL + dR - Vd;    // down 6 rows x 11 cols
        const float fL = uL + dL - hL;    // 11 rows x left 6 cols
        const float fR = uR + dR - hR;    // 11 rows x right 6 cols

        // Candidates in reference kernel-stack order:
        // [LL, LR, RL, RR, L*k, R*k, k*L, k*R]
        float bd = uL * i36 - c0;
        float ba = fabsf(bd);
        float di, ai;
        di = uR * i36 - c0; ai = fabsf(di); if (ai < ba) { ba = ai; bd = di; }
        di = dL * i36 - c0; ai = fabsf(di); if (ai < ba) { ba = ai; bd = di; }
        di = dR * i36 - c0; ai = fabsf(di); if (ai < ba) { ba = ai; bd = di; }
        di = uF * i66 - c0; ai = fabsf(di); if (ai < ba) { ba = ai; bd = di; }
        di = dF * i66 - c0; ai = fabsf(di); if (ai < ba) { ba = ai; bd = di; }
        di = fL * i66 - c0; ai = fabsf(di); if (ai < ba) { ba = ai; bd = di; }
        di = fR * i66 - c0; ai = fabsf(di); if (ai < ba) { ba = ai; bd = di; }

        const int gy = y0 + base + ly;
        if (xok && gy < PH) {
            Dp[gy * PITCH + gx] = c0 + bd;
        }
    }
}

// ---------------- crop planar padded -> HWC output ----------------
__global__ void swf_crop(float* __restrict__ out) {
    int total = H_IMG * W_IMG * C_IMG;
    for (int i = blockIdx.x * blockDim.x + threadIdx.x; i < total;
         i += gridDim.x * blockDim.x) {
        int c = i % C_IMG;
        int t = i / C_IMG;
        int x = t % W_IMG;
        int y = t / W_IMG;
        out[i] = g_U[0][c * PLANE + (y + RAD) * PITCH + (x + RAD)];
    }
}

extern "C" void kernel_launch(void* const* d_in, const int* in_sizes, int n_in,
                              void* d_out, int out_size) {
    const float* img = (const float*)d_in[0];   // (2048,2048,3) f32; kernel tensor d_in[1] hardcoded
    float* out = (float*)d_out;

    {
        int total = C_IMG * PH * PW;
        int threads = 256;
        int blocks = (total + threads - 1) / threads;
        if (blocks > 65535) blocks = 65535;
        swf_pad<<<blocks, threads>>>(img);
    }

    dim3 block(256, 1, 1);
    dim3 grid((PW + TW - 1) / TW, (PH + TH - 1) / TH, C_IMG);
    for (int i = 0; i < NITER; i++) {
        swf_iter<<<grid, block>>>(i & 1);
    }

    {
        int total = H_IMG * W_IMG * C_IMG;
        int threads = 256;
        int blocks = (total + threads - 1) / threads;
        if (blocks > 65535) blocks = 65535;
        swf_crop<<<blocks, threads>>>(out);
    }
}